// round 5
// baseline (speedup 1.0000x reference)
#include <cuda_runtime.h>
#include <cstdint>

// ---------------------------------------------------------------------------
// RNN-T joint network (sm_103 legacy tensor path):
//   XT = x@W_tr + b_tr            [1600, 256]
//   YP = y@W_pr + b_pr            [400, 256]
//   Z  = tf32(tanh(XT[bt] + YP[b,u]))   [160000, 256]
//   out= Z @ W_cls + b_cls        [160000, 1024]
// Joint GEMM: mma.sync tf32, warp tile 64x64 (2x4 warps, 256 thr), CTA 128x256,
// ldmatrix.x4 feeds (conflict-free stride-36), 3-stage cp.async, 1 sync/chunk.
// ---------------------------------------------------------------------------

#define B_  4
#define T_  400
#define U_  100
#define DTR 768
#define DPR 640
#define DJ  256
#define V_  1024
#define M_TOTAL (B_ * T_ * U_)   // 160000

__device__ float g_XT[(size_t)B_ * T_ * DJ];
__device__ float g_YP[(size_t)B_ * U_ * DJ];
__device__ float g_Z[(size_t)M_TOTAL * DJ];   // 164 MB, tf32-rounded
__device__ float g_Wt[(size_t)V_ * DJ];       // tf32(W_cls^T), n-major [V][DJ]

__device__ __forceinline__ float to_tf32(float f) {
    uint32_t u;
    asm("cvt.rna.tf32.f32 %0, %1;" : "=r"(u) : "f"(f));
    return __uint_as_float(u);
}

__device__ __forceinline__ void mma_tf32(float* c, const uint32_t* a, const uint32_t* b) {
    asm volatile(
        "mma.sync.aligned.m16n8k8.row.col.f32.tf32.tf32.f32 "
        "{%0,%1,%2,%3}, {%4,%5,%6,%7}, {%8,%9}, {%0,%1,%2,%3};\n"
        : "+f"(c[0]), "+f"(c[1]), "+f"(c[2]), "+f"(c[3])
        : "r"(a[0]), "r"(a[1]), "r"(a[2]), "r"(a[3]), "r"(b[0]), "r"(b[1]));
}

__device__ __forceinline__ void ldsm_x4(uint32_t& r0, uint32_t& r1, uint32_t& r2,
                                        uint32_t& r3, uint32_t addr) {
    asm volatile("ldmatrix.sync.aligned.m8n8.x4.shared.b16 {%0,%1,%2,%3}, [%4];"
                 : "=r"(r0), "=r"(r1), "=r"(r2), "=r"(r3) : "r"(addr));
}

__device__ __forceinline__ uint32_t smem_u32(const void* p) {
    uint32_t a;
    asm("{ .reg .u64 t; cvta.to.shared.u64 t, %1; cvt.u32.u64 %0, t; }" : "=r"(a) : "l"(p));
    return a;
}

// ---------------------------------------------------------------------------
// Stage 0: Wt[n][k] = tf32(W_cls[k][n])
// ---------------------------------------------------------------------------
__global__ __launch_bounds__(256)
void transpose_w(const float* __restrict__ W, float* __restrict__ Wt) {
    __shared__ float t[32][33];
    int n0 = blockIdx.x * 32, k0 = blockIdx.y * 32;
    int tx = threadIdx.x, ty = threadIdx.y;   // (32, 8)
#pragma unroll
    for (int i = 0; i < 32; i += 8)
        t[ty + i][tx] = to_tf32(W[(size_t)(k0 + ty + i) * V_ + n0 + tx]);
    __syncthreads();
#pragma unroll
    for (int i = 0; i < 32; i += 8)
        Wt[(size_t)(n0 + ty + i) * DJ + k0 + tx] = t[tx][ty + i];
}

// ---------------------------------------------------------------------------
// Stage 1: small fp32 GEMM with bias, C[M,256] = A[M,K] @ W[K,256] + bias
// ---------------------------------------------------------------------------
__global__ __launch_bounds__(256)
void gemm_bias_f32(const float* __restrict__ A, const float* __restrict__ W,
                   const float* __restrict__ bias, float* __restrict__ C,
                   int M, int K) {
    const int N = DJ;
    __shared__ float As[16][68];
    __shared__ float Ws[16][68];

    int m0 = blockIdx.x * 64, n0 = blockIdx.y * 64;
    int tid = threadIdx.x;
    int ty = tid >> 4, tx = tid & 15;

    float acc[4][4];
#pragma unroll
    for (int i = 0; i < 4; i++)
#pragma unroll
        for (int j = 0; j < 4; j++) acc[i][j] = 0.f;

    for (int k0 = 0; k0 < K; k0 += 16) {
        {
            int row = tid >> 2, kc = (tid & 3) << 2;
            float4 v = make_float4(0.f, 0.f, 0.f, 0.f);
            int m = m0 + row;
            if (m < M) v = *(const float4*)(A + (size_t)m * K + k0 + kc);
            As[kc + 0][row] = v.x;
            As[kc + 1][row] = v.y;
            As[kc + 2][row] = v.z;
            As[kc + 3][row] = v.w;
        }
        {
            int kr = tid >> 4, nc = (tid & 15) << 2;
            float4 w = *(const float4*)(W + (size_t)(k0 + kr) * N + n0 + nc);
            *(float4*)&Ws[kr][nc] = w;
        }
        __syncthreads();
#pragma unroll
        for (int kk = 0; kk < 16; kk++) {
            float a[4], b[4];
#pragma unroll
            for (int i = 0; i < 4; i++) a[i] = As[kk][ty * 4 + i];
#pragma unroll
            for (int j = 0; j < 4; j++) b[j] = Ws[kk][tx * 4 + j];
#pragma unroll
            for (int i = 0; i < 4; i++)
#pragma unroll
                for (int j = 0; j < 4; j++) acc[i][j] = fmaf(a[i], b[j], acc[i][j]);
        }
        __syncthreads();
    }
#pragma unroll
    for (int i = 0; i < 4; i++) {
        int m = m0 + ty * 4 + i;
        if (m >= M) continue;
#pragma unroll
        for (int j = 0; j < 4; j++) {
            int n = n0 + tx * 4 + j;
            C[(size_t)m * N + n] = acc[i][j] + bias[n];
        }
    }
}

// ---------------------------------------------------------------------------
// Stage 2: Z = tf32_round(tanh(XT[bt,:] + YP[b*U+u,:]))
// ---------------------------------------------------------------------------
__global__ __launch_bounds__(256)
void z_tanh_kernel(const float* __restrict__ XT, const float* __restrict__ YP,
                   float* __restrict__ Z) {
    int i = blockIdx.x * blockDim.x + threadIdx.x;
    const int total4 = M_TOTAL * (DJ / 4);
    if (i >= total4) return;
    int m = i >> 6;
    int q = i & 63;
    int bt = m / U_;
    int u = m - bt * U_;
    int b = bt / T_;

    float4 xv = *(const float4*)(XT + (size_t)bt * DJ + q * 4);
    float4 yv = *(const float4*)(YP + (size_t)(b * U_ + u) * DJ + q * 4);
    float4 z;
    z.x = to_tf32(tanhf(xv.x + yv.x));
    z.y = to_tf32(tanhf(xv.y + yv.y));
    z.z = to_tf32(tanhf(xv.z + yv.z));
    z.w = to_tf32(tanhf(xv.w + yv.w));
    *(float4*)(Z + (size_t)m * DJ + q * 4) = z;
}

// ---------------------------------------------------------------------------
// Stage 3: out = Z @ W_cls + b_cls  via mma.sync tf32.
// CTA 128M x 256N, 256 threads, 8 warps of 64x64 (2M x 4N).
// A tile [128][36] m-major, B tile [256][36] n-major; stride 36 -> all
// ldmatrix feeds conflict-free. BK=32, 3-stage cp.async, 1 sync/chunk.
// ---------------------------------------------------------------------------
#define BM 128
#define BN 256
#define BK 32
#define TSTRIDE 36
#define A_STAGE_BYTES (BM * TSTRIDE * 4)              // 18432
#define B_STAGE_BYTES (BN * TSTRIDE * 4)              // 36864
#define STAGE_BYTES (A_STAGE_BYTES + B_STAGE_BYTES)   // 55296
#define NSTAGES 3
#define JSMEM (NSTAGES * STAGE_BYTES)                 // 165888

__global__ __launch_bounds__(256, 1)
void joint_gemm_tf32(const float* __restrict__ Z, const float* __restrict__ Wt,
                     const float* __restrict__ bias, float* __restrict__ out) {
    extern __shared__ char sm[];
    const uint32_t smbase = smem_u32(sm);

    const int K = DJ;     // 256
    const int N = V_;     // 1024

    const int n0 = blockIdx.x * BN;
    const int m0 = blockIdx.y * BM;
    const int tid = threadIdx.x;
    const int lane = tid & 31, w = tid >> 5;
    const int warpM = w & 1, warpN = w >> 1;      // 2 x 4
    const int wm0 = warpM * 64, wn0 = warpN * 64;
    const int gid = lane >> 2, tig = lane & 3;

    // ldmatrix per-lane addresses (byte offsets within a stage)
    const int l8 = lane & 7, j = lane >> 3;
    // A: matrix j: rows = wm0 + (j&1)*8 + l8, 16B col chunk = j>>1  [+ kk*4 B]
    const uint32_t aOff = (uint32_t)((wm0 + ((j & 1) << 3) + l8) * TSTRIDE) * 4 +
                          ((uint32_t)(j >> 1) << 4);
    // B: matrix j: nrows = wn0 + (j>>1)*8 + l8, 16B col chunk = j&1
    const uint32_t bOff = (uint32_t)A_STAGE_BYTES +
                          (uint32_t)((wn0 + ((j >> 1) << 3) + l8) * TSTRIDE) * 4 +
                          ((uint32_t)(j & 1) << 4);

    // cp.async ownership (256 threads):
    // A stage: 128 rows x 128B -> thread t: row t>>1, bytes (t&1)*64 + i*16, i<4
    // B stage: 256 rows x 128B -> thread t: row t, 8 x 16B
    const int a_row = tid >> 1;
    const int a_half = tid & 1;                       // which 64B half of the row
    const float* a_src = Z + (size_t)(m0 + a_row) * K + a_half * 16;
    const uint32_t a_dst = smbase + (uint32_t)a_row * (TSTRIDE * 4) + a_half * 64;
    const float* b_src = Wt + (size_t)(n0 + tid) * K;
    const uint32_t b_dst = smbase + A_STAGE_BYTES + (uint32_t)tid * (TSTRIDE * 4);

#define LOAD_TILE(c, s) do { \
    uint32_t _sb = (uint32_t)(s) * STAGE_BYTES; \
    const float* _a = a_src + (c) * BK; \
    const float* _b = b_src + (c) * BK; \
    _Pragma("unroll") \
    for (int i = 0; i < 4; i++) \
        asm volatile("cp.async.cg.shared.global [%0], [%1], 16;" \
                     :: "r"(a_dst + _sb + i * 16), "l"(_a + i * 4)); \
    _Pragma("unroll") \
    for (int i = 0; i < 8; i++) \
        asm volatile("cp.async.cg.shared.global [%0], [%1], 16;" \
                     :: "r"(b_dst + _sb + i * 16), "l"(_b + i * 4)); \
    asm volatile("cp.async.commit_group;" ::: "memory"); \
} while (0)

    float acc[4][8][4];
#pragma unroll
    for (int fm = 0; fm < 4; fm++)
#pragma unroll
        for (int fn = 0; fn < 8; fn++)
#pragma unroll
            for (int r = 0; r < 4; r++) acc[fm][fn][r] = 0.f;

    LOAD_TILE(0, 0);
    LOAD_TILE(1, 1);

#pragma unroll 1
    for (int c = 0; c < 8; c++) {
        if (c < 7) asm volatile("cp.async.wait_group 1;" ::: "memory");
        else       asm volatile("cp.async.wait_group 0;" ::: "memory");
        __syncthreads();
        if (c + 2 < 8) LOAD_TILE(c + 2, (c + 2) % NSTAGES);

        const uint32_t stg = (uint32_t)(c % NSTAGES) * STAGE_BYTES;
        const uint32_t aB = smbase + stg + aOff;
        const uint32_t bB = smbase + stg + bOff;
#pragma unroll
        for (int kk = 0; kk < BK; kk += 8) {
            uint32_t a[4][4], b[8][2];
#pragma unroll
            for (int fm = 0; fm < 4; fm++)
                ldsm_x4(a[fm][0], a[fm][1], a[fm][2], a[fm][3],
                        aB + (uint32_t)fm * (16 * TSTRIDE * 4) + (uint32_t)kk * 4);
#pragma unroll
            for (int p = 0; p < 4; p++)
                ldsm_x4(b[2 * p][0], b[2 * p][1], b[2 * p + 1][0], b[2 * p + 1][1],
                        bB + (uint32_t)p * (16 * TSTRIDE * 4) + (uint32_t)kk * 4);
#pragma unroll
            for (int fm = 0; fm < 4; fm++)
#pragma unroll
                for (int fn = 0; fn < 8; fn++) mma_tf32(acc[fm][fn], a[fm], b[fn]);
        }
    }
#undef LOAD_TILE

    // epilogue: bias + store
#pragma unroll
    for (int fm = 0; fm < 4; fm++) {
        int r0 = m0 + wm0 + fm * 16 + gid;
#pragma unroll
        for (int fn = 0; fn < 8; fn++) {
            int cidx = n0 + wn0 + fn * 8 + 2 * tig;
            float bv0 = __ldg(bias + cidx);
            float bv1 = __ldg(bias + cidx + 1);
            float2 v0 = make_float2(acc[fm][fn][0] + bv0, acc[fm][fn][1] + bv1);
            float2 v1 = make_float2(acc[fm][fn][2] + bv0, acc[fm][fn][3] + bv1);
            *(float2*)(out + (size_t)r0 * N + cidx) = v0;
            *(float2*)(out + (size_t)(r0 + 8) * N + cidx) = v1;
        }
    }
}

// ---------------------------------------------------------------------------
extern "C" void kernel_launch(void* const* d_in, const int* in_sizes, int n_in,
                              void* d_out, int out_size) {
    const float* x     = (const float*)d_in[0];
    const float* y     = (const float*)d_in[1];
    const float* W_tr  = (const float*)d_in[2];
    const float* b_tr  = (const float*)d_in[3];
    const float* W_pr  = (const float*)d_in[4];
    const float* b_pr  = (const float*)d_in[5];
    const float* W_cls = (const float*)d_in[6];
    const float* b_cls = (const float*)d_in[7];
    float* out = (float*)d_out;

    void *pXT, *pYP, *pZ, *pWt;
    cudaGetSymbolAddress(&pXT, g_XT);
    cudaGetSymbolAddress(&pYP, g_YP);
    cudaGetSymbolAddress(&pZ, g_Z);
    cudaGetSymbolAddress(&pWt, g_Wt);

    // Wt = tf32(W_cls^T)
    {
        dim3 grid(V_ / 32, DJ / 32);
        transpose_w<<<grid, dim3(32, 8)>>>(W_cls, (float*)pWt);
    }
    // XT = x @ W_tr + b_tr
    {
        dim3 grid((B_ * T_ + 63) / 64, DJ / 64);
        gemm_bias_f32<<<grid, 256>>>(x, W_tr, b_tr, (float*)pXT, B_ * T_, DTR);
    }
    // YP = y @ W_pr + b_pr
    {
        dim3 grid((B_ * U_ + 63) / 64, DJ / 64);
        gemm_bias_f32<<<grid, 256>>>(y, W_pr, b_pr, (float*)pYP, B_ * U_, DPR);
    }
    // Z = tf32(tanh(XT + YP))
    {
        int total4 = M_TOTAL * (DJ / 4);
        z_tanh_kernel<<<(total4 + 255) / 256, 256>>>((const float*)pXT,
                                                     (const float*)pYP, (float*)pZ);
    }
    // out = Z @ W_cls + b_cls
    {
        cudaFuncSetAttribute(joint_gemm_tf32, cudaFuncAttributeMaxDynamicSharedMemorySize,
                             JSMEM);
        dim3 grid(V_ / BN, M_TOTAL / BM);   // (4, 1250), N fastest for Z reuse
        joint_gemm_tf32<<<grid, 256, JSMEM>>>((const float*)pZ, (const float*)pWt,
                                              b_cls, out);
    }
}